// round 12
// baseline (speedup 1.0000x reference)
#include <cuda_runtime.h>
#include <cuda_bf16.h>
#include <cstddef>
#include <cstdint>

// JPEG 8x8 block DCT + quantization scaling.
// out[b, k*8+l, hb, wb] = DCT2(x-128)[k][l] / (factor(QF_b) * Q[k][l])
// One thread per 8x8 block.
// Input loads: ld.global.nc.L2::evict_last.v8.b32 — one 32B load per block row
// (8 LDG/thread) and pins the 64MB image in L2 across graph replays.
// Output stores: plain st.global (R12 bisect: __stcs removed).

#define C1A 0.49039264020161522f   // 0.5*cos(1*pi/16)
#define C1B 0.46193976625564337f   // 0.5*cos(2*pi/16)
#define C1C 0.41573480615127262f   // 0.5*cos(3*pi/16)
#define C1D 0.35355339059327376f   // 1/(2*sqrt(2))
#define C1E 0.27778511650980114f   // 0.5*cos(5*pi/16)
#define C1F 0.19134171618254489f   // 0.5*cos(6*pi/16)
#define C1G 0.09754516100806417f   // 0.5*cos(7*pi/16)

// 256-bit load with L2 evict_last: loads one full 8-float block row.
__device__ __forceinline__ void ldg_row_keep(const float* p, float* r)
{
    asm volatile("ld.global.nc.L2::evict_last.v8.b32 "
                 "{%0,%1,%2,%3,%4,%5,%6,%7}, [%8];"
                 : "=f"(r[0]), "=f"(r[1]), "=f"(r[2]), "=f"(r[3]),
                   "=f"(r[4]), "=f"(r[5]), "=f"(r[6]), "=f"(r[7])
                 : "l"(p));
}

// In-place 8-point orthonormal DCT-II via even/odd symmetry (36 fma-pipe ops).
#define DCT8(v0, v1, v2, v3, v4, v5, v6, v7)                                  \
    {                                                                          \
        float s0 = (v0) + (v7), s1 = (v1) + (v6);                              \
        float s2 = (v2) + (v5), s3 = (v3) + (v4);                              \
        float d0 = (v0) - (v7), d1 = (v1) - (v6);                              \
        float d2 = (v2) - (v5), d3 = (v3) - (v4);                              \
        float u0 = s0 + s3, u1 = s1 + s2;                                      \
        float w0 = s0 - s3, w1 = s1 - s2;                                      \
        (v0) = C1D * (u0 + u1);                                                \
        (v4) = C1D * (u0 - u1);                                                \
        (v2) = C1B * w0 + C1F * w1;                                            \
        (v6) = C1F * w0 - C1B * w1;                                            \
        (v1) = C1A * d0 + C1C * d1 + C1E * d2 + C1G * d3;                      \
        (v3) = C1C * d0 - C1G * d1 - C1A * d2 - C1E * d3;                      \
        (v5) = C1E * d0 - C1A * d1 + C1G * d2 + C1C * d3;                      \
        (v7) = C1G * d0 - C1E * d1 + C1C * d2 - C1A * d3;                      \
    }

__global__ void __launch_bounds__(128)
jpeg_dct_kernel(const float* __restrict__ img,
                const float* __restrict__ qf,
                float* __restrict__ out)
{
    // 100 / luminance_quant_table (folds to FMUL-imm after unroll)
    const float INVQ[8][8] = {
        {6.25f,       9.0909090909090910f, 10.0f,      6.25f,       4.1666666666666667f, 2.5f,        1.9607843137254901f, 1.6393442622950820f},
        {8.3333333333333333f, 8.3333333333333333f, 7.1428571428571432f, 5.2631578947368425f, 3.8461538461538463f, 1.7241379310344827f, 1.6666666666666667f, 1.8181818181818181f},
        {7.1428571428571432f, 7.6923076923076925f, 6.25f,      4.1666666666666667f, 2.5f,       1.7543859649122806f, 1.4492753623188406f, 1.7857142857142858f},
        {7.1428571428571432f, 5.8823529411764710f, 4.5454545454545459f, 3.4482758620689657f, 1.9607843137254901f, 1.1494252873563218f, 1.25f,      1.6129032258064515f},
        {5.5555555555555554f, 4.5454545454545459f, 2.7027027027027026f, 1.7857142857142858f, 1.4705882352941178f, 0.91743119266055051f, 0.97087378640776700f, 1.2987012987012987f},
        {4.1666666666666667f, 2.7777777777777777f, 1.8181818181818181f, 1.5625f,    1.2345679012345678f, 0.96153846153846156f, 0.88495575221238942f, 1.0869565217391304f},
        {2.0408163265306123f, 1.5625f,    1.2820512820512820f, 1.1494252873563218f, 0.97087378640776700f, 0.82644628099173556f, 0.83333333333333337f, 0.99009900990099009f},
        {1.3888888888888888f, 1.0869565217391304f, 1.0526315789473684f, 1.0204081632653061f, 0.89285714285714285f, 1.0f,       0.97087378640776700f, 1.0101010101010102f}
    };

    int tid = blockIdx.x * blockDim.x + threadIdx.x;
    int wb = tid & 127;          // block col  (fastest -> coalesced)
    int hb = (tid >> 7) & 127;   // block row
    int b  = tid >> 14;          // batch

    const float* src = img + ((size_t)b << 20) + ((size_t)hb << 13) + (wb << 3);

    // Load the 8x8 block: 8 x 256-bit loads (one per row), L2-resident.
    float x[8][8];
#pragma unroll
    for (int r = 0; r < 8; r++) {
        ldg_row_keep(src + r * 1024, x[r]);
    }

    float q = __ldg(&qf[b]);
    float factor = (q < 50.0f) ? (5000.0f / q) : (200.0f - 2.0f * q);
    float rf = 1.0f / factor;

    // First pass: DCT along r (per column c), in place.
#pragma unroll
    for (int c = 0; c < 8; c++) {
        DCT8(x[0][c], x[1][c], x[2][c], x[3][c],
             x[4][c], x[5][c], x[6][c], x[7][c]);
    }

    // Fold the -128 pixel shift into the DC row; scale everything by rf.
#pragma unroll
    for (int c = 0; c < 8; c++) {
        x[0][c] = (x[0][c] - 362.03867196751236f) * rf;
    }
#pragma unroll
    for (int k = 1; k < 8; k++) {
#pragma unroll
        for (int c = 0; c < 8; c++) x[k][c] *= rf;
    }

    // Second pass: DCT along c (per row k), scale by invQ, plain store.
    float* dst = out + ((size_t)b << 20) + (hb << 7) + wb;
#pragma unroll
    for (int k = 0; k < 8; k++) {
        float v0 = x[k][0], v1 = x[k][1], v2 = x[k][2], v3 = x[k][3];
        float v4 = x[k][4], v5 = x[k][5], v6 = x[k][6], v7 = x[k][7];
        DCT8(v0, v1, v2, v3, v4, v5, v6, v7);
        float* dk = dst + ((size_t)(k << 3) << 14);
        dk[0 << 14] = v0 * INVQ[k][0];
        dk[1 << 14] = v1 * INVQ[k][1];
        dk[2 << 14] = v2 * INVQ[k][2];
        dk[3 << 14] = v3 * INVQ[k][3];
        dk[4 << 14] = v4 * INVQ[k][4];
        dk[5 << 14] = v5 * INVQ[k][5];
        dk[6 << 14] = v6 * INVQ[k][6];
        dk[7 << 14] = v7 * INVQ[k][7];
    }
}

extern "C" void kernel_launch(void* const* d_in, const int* in_sizes, int n_in,
                              void* d_out, int out_size)
{
    const float* img = (const float*)d_in[0];
    const float* qf  = (const float*)d_in[1];
    float* out = (float*)d_out;

    int B = in_sizes[0] >> 20;          // elements / (1024*1024)
    int total_threads = B * 128 * 128;  // one thread per 8x8 block
    int block = 128;
    int grid = (total_threads + block - 1) / block;
    jpeg_dct_kernel<<<grid, block>>>(img, qf, out);
}

// round 15
// speedup vs baseline: 1.1116x; 1.1116x over previous
#include <cuda_runtime.h>
#include <cuda_bf16.h>
#include <cstddef>
#include <cstdint>

// JPEG 8x8 block DCT + quantization scaling.
// out[b, k*8+l, hb, wb] = DCT2(x-128)[k][l] / (factor(QF_b) * Q[k][l])
// One thread per 8x8 block.
// R13: row-direction DCT FIRST, immediately after each row's load arrives
// (each row depends on exactly one 256-bit load -> compute overlaps the
// remaining loads' latency). Column-direction DCT second, storing each
// column's 8 outputs right after its butterfly.
// Loads: ld.global.nc.L2::evict_last.v8.b32 (input pinned in L2).
// Stores: __stcs streaming (keeps output from evicting the input).

#define C1A 0.49039264020161522f   // 0.5*cos(1*pi/16)
#define C1B 0.46193976625564337f   // 0.5*cos(2*pi/16)
#define C1C 0.41573480615127262f   // 0.5*cos(3*pi/16)
#define C1D 0.35355339059327376f   // 1/(2*sqrt(2))
#define C1E 0.27778511650980114f   // 0.5*cos(5*pi/16)
#define C1F 0.19134171618254489f   // 0.5*cos(6*pi/16)
#define C1G 0.09754516100806417f   // 0.5*cos(7*pi/16)

// 256-bit load with L2 evict_last: one full 8-float block row.
__device__ __forceinline__ void ldg_row_keep(const float* p, float* r)
{
    asm volatile("ld.global.nc.L2::evict_last.v8.b32 "
                 "{%0,%1,%2,%3,%4,%5,%6,%7}, [%8];"
                 : "=f"(r[0]), "=f"(r[1]), "=f"(r[2]), "=f"(r[3]),
                   "=f"(r[4]), "=f"(r[5]), "=f"(r[6]), "=f"(r[7])
                 : "l"(p));
}

// In-place 8-point orthonormal DCT-II via even/odd symmetry (36 fma-pipe ops).
#define DCT8(v0, v1, v2, v3, v4, v5, v6, v7)                                  \
    {                                                                          \
        float s0 = (v0) + (v7), s1 = (v1) + (v6);                              \
        float s2 = (v2) + (v5), s3 = (v3) + (v4);                              \
        float d0 = (v0) - (v7), d1 = (v1) - (v6);                              \
        float d2 = (v2) - (v5), d3 = (v3) - (v4);                              \
        float u0 = s0 + s3, u1 = s1 + s2;                                      \
        float w0 = s0 - s3, w1 = s1 - s2;                                      \
        (v0) = C1D * (u0 + u1);                                                \
        (v4) = C1D * (u0 - u1);                                                \
        (v2) = C1B * w0 + C1F * w1;                                            \
        (v6) = C1F * w0 - C1B * w1;                                            \
        (v1) = C1A * d0 + C1C * d1 + C1E * d2 + C1G * d3;                      \
        (v3) = C1C * d0 - C1G * d1 - C1A * d2 - C1E * d3;                      \
        (v5) = C1E * d0 - C1A * d1 + C1G * d2 + C1C * d3;                      \
        (v7) = C1G * d0 - C1E * d1 + C1C * d2 - C1A * d3;                      \
    }

__global__ void __launch_bounds__(128)
jpeg_dct_kernel(const float* __restrict__ img,
                const float* __restrict__ qf,
                float* __restrict__ out)
{
    // 100 / luminance_quant_table (folds to FMUL-imm after unroll)
    const float INVQ[8][8] = {
        {6.25f,       9.0909090909090910f, 10.0f,      6.25f,       4.1666666666666667f, 2.5f,        1.9607843137254901f, 1.6393442622950820f},
        {8.3333333333333333f, 8.3333333333333333f, 7.1428571428571432f, 5.2631578947368425f, 3.8461538461538463f, 1.7241379310344827f, 1.6666666666666667f, 1.8181818181818181f},
        {7.1428571428571432f, 7.6923076923076925f, 6.25f,      4.1666666666666667f, 2.5f,       1.7543859649122806f, 1.4492753623188406f, 1.7857142857142858f},
        {7.1428571428571432f, 5.8823529411764710f, 4.5454545454545459f, 3.4482758620689657f, 1.9607843137254901f, 1.1494252873563218f, 1.25f,      1.6129032258064515f},
        {5.5555555555555554f, 4.5454545454545459f, 2.7027027027027026f, 1.7857142857142858f, 1.4705882352941178f, 0.91743119266055051f, 0.97087378640776700f, 1.2987012987012987f},
        {4.1666666666666667f, 2.7777777777777777f, 1.8181818181818181f, 1.5625f,    1.2345679012345678f, 0.96153846153846156f, 0.88495575221238942f, 1.0869565217391304f},
        {2.0408163265306123f, 1.5625f,    1.2820512820512820f, 1.1494252873563218f, 0.97087378640776700f, 0.82644628099173556f, 0.83333333333333337f, 0.99009900990099009f},
        {1.3888888888888888f, 1.0869565217391304f, 1.0526315789473684f, 1.0204081632653061f, 0.89285714285714285f, 1.0f,       0.97087378640776700f, 1.0101010101010102f}
    };

    int tid = blockIdx.x * blockDim.x + threadIdx.x;
    int wb = tid & 127;          // block col  (fastest -> coalesced)
    int hb = (tid >> 7) & 127;   // block row
    int b  = tid >> 14;          // batch

    const float* src = img + ((size_t)b << 20) + ((size_t)hb << 13) + (wb << 3);

    float q = __ldg(&qf[b]);
    float factor = (q < 50.0f) ? (5000.0f / q) : (200.0f - 2.0f * q);
    float rf = 1.0f / factor;

    // Pass 1: load each row and immediately DCT along the row (c-direction),
    // fold the -128 shift into the row's DC term, and scale by rf.
    // Each row depends on exactly one load -> compute hides load latency.
    float x[8][8];
#pragma unroll
    for (int r = 0; r < 8; r++) {
        ldg_row_keep(src + r * 1024, x[r]);
        DCT8(x[r][0], x[r][1], x[r][2], x[r][3],
             x[r][4], x[r][5], x[r][6], x[r][7]);
        x[r][0] = (x[r][0] - 362.03867196751236f) * rf;  // 128*8*C1D folded
        x[r][1] *= rf; x[r][2] *= rf; x[r][3] *= rf;
        x[r][4] *= rf; x[r][5] *= rf; x[r][6] *= rf; x[r][7] *= rf;
    }

    // Pass 2: DCT along r for each column l; store that column's 8 outputs
    // (planes k*8+l, k=0..7) right away.
    float* dst = out + ((size_t)b << 20) + (hb << 7) + wb;
#pragma unroll
    for (int l = 0; l < 8; l++) {
        float v0 = x[0][l], v1 = x[1][l], v2 = x[2][l], v3 = x[3][l];
        float v4 = x[4][l], v5 = x[5][l], v6 = x[6][l], v7 = x[7][l];
        DCT8(v0, v1, v2, v3, v4, v5, v6, v7);
        float* dl = dst + ((size_t)l << 14);
        __stcs(dl + (size_t)(0 * 8) * 16384, v0 * INVQ[0][l]);
        __stcs(dl + (size_t)(1 * 8) * 16384, v1 * INVQ[1][l]);
        __stcs(dl + (size_t)(2 * 8) * 16384, v2 * INVQ[2][l]);
        __stcs(dl + (size_t)(3 * 8) * 16384, v3 * INVQ[3][l]);
        __stcs(dl + (size_t)(4 * 8) * 16384, v4 * INVQ[4][l]);
        __stcs(dl + (size_t)(5 * 8) * 16384, v5 * INVQ[5][l]);
        __stcs(dl + (size_t)(6 * 8) * 16384, v6 * INVQ[6][l]);
        __stcs(dl + (size_t)(7 * 8) * 16384, v7 * INVQ[7][l]);
    }
}

extern "C" void kernel_launch(void* const* d_in, const int* in_sizes, int n_in,
                              void* d_out, int out_size)
{
    const float* img = (const float*)d_in[0];
    const float* qf  = (const float*)d_in[1];
    float* out = (float*)d_out;

    int B = in_sizes[0] >> 20;          // elements / (1024*1024)
    int total_threads = B * 128 * 128;  // one thread per 8x8 block
    int block = 128;
    int grid = (total_threads + block - 1) / block;
    jpeg_dct_kernel<<<grid, block>>>(img, qf, out);
}